// round 3
// baseline (speedup 1.0000x reference)
#include <cuda_runtime.h>

// Problem constants
#define B_SZ   32
#define CIN    128
#define H_IN   112
#define W_IN   112
#define COUT   256
#define OHW    55          // output height == width
#define STRIDE 2
#define M_TOT  (B_SZ * OHW * OHW)   // 96800
#define K_TOT  (CIN * 9)            // 1152
#define OPIX   (OHW * OHW)          // 3025
#define INHW   (H_IN * W_IN)        // 12544

// GEMM tiling
#define BM 128
#define BN 128
#define BK 16
#define TM 8
#define TN 8
#define NTHREADS 256
#define PAD 4

__global__ __launch_bounds__(NTHREADS, 2)
void conv_igemm_kernel(const float* __restrict__ x,
                       const float* __restrict__ w,
                       float* __restrict__ out)
{
    __shared__ float As[BK][BM + PAD];
    __shared__ float Bs[BK][BN + PAD];

    const int tid = threadIdx.x;
    const int m0  = blockIdx.y * BM;
    const int n0  = blockIdx.x * BN;

    // ---- A-load assignment: one fixed m per thread, 8 k's per iteration ----
    const int  mA    = tid & 127;
    const int  kOffA = tid >> 7;                  // 0 or 1
    const int  mGlob = m0 + mA;
    const bool mValid = (mGlob < M_TOT);
    {
    }
    const int mc  = mValid ? mGlob : 0;
    const int bA  = mc / OPIX;
    const int rA  = mc - bA * OPIX;
    const int ohA = rA / OHW;
    const int owA = rA - ohA * OHW;
    const float* xbase = x + ((size_t)bA * CIN) * INHW
                           + (size_t)(ohA * STRIDE) * W_IN
                           + (owA * STRIDE);

    // ---- B-load assignment: n = tid>>1, k-offset = (tid&1)*8 ----
    const int nB    = tid >> 1;
    const int kOffB = (tid & 1) * 8;
    const float* wbase = w + (size_t)(n0 + nB) * K_TOT + kOffB;

    // ---- compute-thread coords ----
    const int ty = tid >> 4;   // 0..15 -> m rows ty*8..ty*8+7
    const int tx = tid & 15;   // 0..15 -> n cols tx*8..tx*8+7

    float acc[TM][TN];
    #pragma unroll
    for (int i = 0; i < TM; i++)
        #pragma unroll
        for (int j = 0; j < TN; j++)
            acc[i][j] = 0.0f;

    float aReg[8];
    float bReg[8];

    const int KT = K_TOT / BK;   // 72

    // ---- prefetch tile 0 into registers ----
    #pragma unroll
    for (int i = 0; i < 8; i++) {
        const int k   = kOffA + 2 * i;          // kt = 0
        const int cin = k / 9;
        const int rs  = k - cin * 9;
        const int r   = rs / 3;
        const int s   = rs - r * 3;
        aReg[i] = mValid ? xbase[cin * INHW + r * W_IN + s] : 0.0f;
    }
    #pragma unroll
    for (int i = 0; i < 8; i++)
        bReg[i] = wbase[i];

    for (int kt = 0; kt < KT; kt++) {
        // ---- store prefetched regs into smem ----
        #pragma unroll
        for (int i = 0; i < 8; i++)
            As[kOffA + 2 * i][mA] = aReg[i];
        #pragma unroll
        for (int i = 0; i < 8; i++)
            Bs[kOffB + i][nB] = bReg[i];
        __syncthreads();

        // ---- issue next tile's global loads (regs only) ----
        if (kt + 1 < KT) {
            const int kbase = (kt + 1) * BK;
            #pragma unroll
            for (int i = 0; i < 8; i++) {
                const int k   = kbase + kOffA + 2 * i;
                const int cin = k / 9;
                const int rs  = k - cin * 9;
                const int r   = rs / 3;
                const int s   = rs - r * 3;
                aReg[i] = mValid ? xbase[cin * INHW + r * W_IN + s] : 0.0f;
            }
            #pragma unroll
            for (int i = 0; i < 8; i++)
                bReg[i] = wbase[kbase + i];
        }

        // ---- compute on current smem tile ----
        #pragma unroll
        for (int kk = 0; kk < BK; kk++) {
            float afr[TM], bfr[TN];
            #pragma unroll
            for (int i = 0; i < TM; i++)
                afr[i] = As[kk][ty * TM + i];
            #pragma unroll
            for (int j = 0; j < TN; j++)
                bfr[j] = Bs[kk][tx * TN + j];
            #pragma unroll
            for (int i = 0; i < TM; i++)
                #pragma unroll
                for (int j = 0; j < TN; j++)
                    acc[i][j] = fmaf(afr[i], bfr[j], acc[i][j]);
        }
        __syncthreads();
    }

    // ---- epilogue: scatter to NCHW output ----
    #pragma unroll
    for (int i = 0; i < TM; i++) {
        const int m = m0 + ty * TM + i;
        if (m < M_TOT) {
            const int b2  = m / OPIX;
            const int r2  = m - b2 * OPIX;
            const int oh2 = r2 / OHW;
            const int ow2 = r2 - oh2 * OHW;
            float* o = out + ((size_t)(b2 * COUT + n0 + tx * TN) * OHW + oh2) * OHW + ow2;
            #pragma unroll
            for (int j = 0; j < TN; j++)
                o[(size_t)j * OPIX] = acc[i][j];
        }
    }
}

extern "C" void kernel_launch(void* const* d_in, const int* in_sizes, int n_in,
                              void* d_out, int out_size)
{
    const float* x = (const float*)d_in[0];
    const float* w = (const float*)d_in[1];
    float* out = (float*)d_out;

    dim3 grid(COUT / BN, (M_TOT + BM - 1) / BM);   // (2, 757)
    conv_igemm_kernel<<<grid, NTHREADS>>>(x, w, out);
}

// round 5
// speedup vs baseline: 3.1778x; 3.1778x over previous
#include <cuda_runtime.h>
#include <cstdint>

// ---------------- problem constants ----------------
#define B_SZ   32
#define CIN    128
#define H_IN   112
#define W_IN   112
#define COUT   256
#define OHW    55
#define STRIDE 2
#define M_TOT  (B_SZ * OHW * OHW)   // 96800
#define K_TOT  (CIN * 9)            // 1152
#define OPIX   (OHW * OHW)          // 3025
#define INHW   (H_IN * W_IN)        // 12544

// ---------------- GEMM tiling ----------------
#define BM 128
#define BN 256
#define BK 32
#define NT 256
#define KTILES (K_TOT / BK)         // 36

#define ASTRIDE 36                  // floats per A smem row (conflict-free)
#define BSTRIDE 36                  // floats per B smem row
#define A_TILE_F (BM * ASTRIDE)     // 4608 floats
#define B_TILE_F (BN * BSTRIDE)     // 9216 floats
#define SMEM_FLOATS (2 * (A_TILE_F + B_TILE_F))   // 27648
#define SMEM_BYTES  (SMEM_FLOATS * 4)             // 110592

__device__ __forceinline__ uint32_t smem_u32(const void* p) {
    uint32_t a;
    asm("{ .reg .u64 t; cvta.to.shared.u64 t, %1; cvt.u32.u64 %0, t; }" : "=r"(a) : "l"(p));
    return a;
}
__device__ __forceinline__ uint32_t to_tf32(float f) {
    uint32_t u;
    asm("cvt.rna.tf32.f32 %0, %1;" : "=r"(u) : "f"(f));
    return u;
}

#define CP_ASYNC4(dst, src, sz) \
    asm volatile("cp.async.ca.shared.global [%0], [%1], 4, %2;" \
                 :: "r"(dst), "l"(src), "r"(sz) : "memory")
#define CP_ASYNC16(dst, src) \
    asm volatile("cp.async.cg.shared.global [%0], [%1], 16;" \
                 :: "r"(dst), "l"(src) : "memory")
#define CP_COMMIT()  asm volatile("cp.async.commit_group;" ::: "memory")
#define CP_WAIT1()   asm volatile("cp.async.wait_group 1;"  ::: "memory")
#define CP_WAIT0()   asm volatile("cp.async.wait_group 0;"  ::: "memory")

__device__ __forceinline__ void mma_tf32(float& c0, float& c1, float& c2, float& c3,
                                         uint32_t a0, uint32_t a1, uint32_t a2, uint32_t a3,
                                         uint32_t b0, uint32_t b1) {
    asm volatile("mma.sync.aligned.m16n8k8.row.col.f32.tf32.tf32.f32 "
                 "{%0,%1,%2,%3}, {%4,%5,%6,%7}, {%8,%9}, {%0,%1,%2,%3};"
                 : "+f"(c0), "+f"(c1), "+f"(c2), "+f"(c3)
                 : "r"(a0), "r"(a1), "r"(a2), "r"(a3), "r"(b0), "r"(b1));
}

__global__ __launch_bounds__(NT, 1)
void conv_mma_tf32_kernel(const float* __restrict__ x,
                          const float* __restrict__ w,
                          float* __restrict__ out)
{
    extern __shared__ float sm[];
    const uint32_t sbase = smem_u32(sm);

    const int tid  = threadIdx.x;
    const int lane = tid & 31;
    const int wid  = tid >> 5;
    const int gid  = lane >> 2;     // 0..7
    const int qid  = lane & 3;      // 0..3
    const int warp_m = wid & 1;     // 0..1 -> m offset warp_m*64
    const int warp_n = wid >> 1;    // 0..3 -> n offset warp_n*64
    const int m0 = blockIdx.x * BM;

    // smem stage offsets (in floats)
    const int Aoff[2] = {0, A_TILE_F};
    const int Boff[2] = {2 * A_TILE_F, 2 * A_TILE_F + B_TILE_F};

    // ---- A gather assignment: thread owns m-row = tid>>1, 16 k's ----
    const int  mRow   = tid >> 1;
    const int  kHalf  = (tid & 1) * 16;
    const int  mG     = m0 + mRow;
    const bool mValid = (mG < M_TOT);
    const int  srcsz  = mValid ? 4 : 0;
    const int  mc  = mValid ? mG : (M_TOT - 1);
    const int  bA  = mc / OPIX;
    const int  rA  = mc - bA * OPIX;
    const int  ohA = rA / OHW;
    const int  owA = rA - ohA * OHW;
    const float* xrow = x + (size_t)bA * CIN * INHW
                          + (size_t)(ohA * STRIDE) * W_IN + owA * STRIDE;

    auto load_a = [&](int buf, int ktbase) {
        const uint32_t dst0 = sbase + (uint32_t)(Aoff[buf] + mRow * ASTRIDE + kHalf) * 4u;
        #pragma unroll
        for (int j = 0; j < 16; j++) {
            const int k   = ktbase + kHalf + j;
            const int cin = k / 9;
            const int rs  = k - cin * 9;
            const int r   = rs / 3;
            const int s   = rs - r * 3;
            const float* g = xrow + (size_t)cin * INHW + r * W_IN + s;
            CP_ASYNC4(dst0 + 4u * j, g, srcsz);
        }
    };
    auto load_b = [&](int buf, int ktbase) {
        #pragma unroll
        for (int p = 0; p < 8; p++) {
            const int idx = tid + NT * p;
            const int row = idx >> 3;
            const int q   = idx & 7;
            const float* g = w + (size_t)row * K_TOT + ktbase + q * 4;
            const uint32_t dst = sbase + (uint32_t)(Boff[buf] + row * BSTRIDE + q * 4) * 4u;
            CP_ASYNC16(dst, g);
        }
    };

    float acc[4][8][4];
    #pragma unroll
    for (int i = 0; i < 4; i++)
        #pragma unroll
        for (int j = 0; j < 8; j++)
            #pragma unroll
            for (int e = 0; e < 4; e++)
                acc[i][j][e] = 0.0f;

    // ---- prologue: prime 2 stages ----
    load_a(0, 0);  load_b(0, 0);  CP_COMMIT();
    load_a(1, BK); load_b(1, BK); CP_COMMIT();

    for (int kt = 0; kt < KTILES; kt++) {
        const int buf = kt & 1;
        if (kt < KTILES - 2) CP_WAIT1(); else CP_WAIT0();
        __syncthreads();

        const float* A = sm + Aoff[buf];
        const float* Bt = sm + Boff[buf];

        #pragma unroll
        for (int step = 0; step < 4; step++) {
            const int kk = step * 8;
            uint32_t af[4][4];
            #pragma unroll
            for (int mt = 0; mt < 4; mt++) {
                const float* ap = A + (warp_m * 64 + mt * 16 + gid) * ASTRIDE + kk + qid;
                af[mt][0] = to_tf32(ap[0]);
                af[mt][1] = to_tf32(ap[8 * ASTRIDE]);
                af[mt][2] = to_tf32(ap[4]);
                af[mt][3] = to_tf32(ap[8 * ASTRIDE + 4]);
            }
            uint32_t bf[8][2];
            #pragma unroll
            for (int nt = 0; nt < 8; nt++) {
                const float* bp = Bt + (warp_n * 64 + nt * 8 + gid) * BSTRIDE + kk + qid;
                bf[nt][0] = to_tf32(bp[0]);
                bf[nt][1] = to_tf32(bp[4]);
            }
            #pragma unroll
            for (int mt = 0; mt < 4; mt++)
                #pragma unroll
                for (int nt = 0; nt < 8; nt++)
                    mma_tf32(acc[mt][nt][0], acc[mt][nt][1], acc[mt][nt][2], acc[mt][nt][3],
                             af[mt][0], af[mt][1], af[mt][2], af[mt][3],
                             bf[nt][0], bf[nt][1]);
        }
        __syncthreads();

        if (kt + 2 < KTILES) {
            load_a(buf, (kt + 2) * BK);
            load_b(buf, (kt + 2) * BK);
            CP_COMMIT();
        }
    }

    // ---- epilogue: direct register -> gmem scatter ----
    #pragma unroll
    for (int mt = 0; mt < 4; mt++) {
        const int mb = m0 + warp_m * 64 + mt * 16;
        #pragma unroll
        for (int half = 0; half < 2; half++) {
            const int m = mb + gid + half * 8;
            if (m < M_TOT) {
                const int b2  = m / OPIX;
                const int r2  = m - b2 * OPIX;
                const int oh2 = r2 / OHW;
                const int ow2 = r2 - oh2 * OHW;
                float* op = out + (size_t)b2 * COUT * OPIX + (size_t)oh2 * OHW + ow2;
                const int ncol0 = warp_n * 64 + qid * 2;
                #pragma unroll
                for (int nt = 0; nt < 8; nt++) {
                    const int n = ncol0 + nt * 8;
                    op[(size_t)n * OPIX]       = acc[mt][nt][half * 2 + 0];
                    op[(size_t)(n + 1) * OPIX] = acc[mt][nt][half * 2 + 1];
                }
            }
        }
    }
}

extern "C" void kernel_launch(void* const* d_in, const int* in_sizes, int n_in,
                              void* d_out, int out_size)
{
    const float* x = (const float*)d_in[0];
    const float* w = (const float*)d_in[1];
    float* out = (float*)d_out;

    cudaFuncSetAttribute(conv_mma_tf32_kernel,
                         cudaFuncAttributeMaxDynamicSharedMemorySize, SMEM_BYTES);

    const int grid = (M_TOT + BM - 1) / BM;   // 757
    conv_mma_tf32_kernel<<<grid, NT, SMEM_BYTES>>>(x, w, out);
}